// round 2
// baseline (speedup 1.0000x reference)
#include <cuda_runtime.h>
#include <math.h>

// ---------------- problem constants ----------------
#define BATCH   16
#define LQ      300
#define CDIM    256
#define NHEADS  8
#define NLEV    3
#define NPTS    4
#define HDIM    32            // CDIM / NHEADS
#define LV      8400          // 80*80 + 40*40 + 20*20
#define TPQ     (NHEADS*NLEV*NPTS)   // 96
#define NQ      (BATCH*LQ)           // 4800

// level geometry
__device__ __constant__ int c_lvl_w[NLEV]     = {80, 40, 20};
__device__ __constant__ int c_lvl_h[NLEV]     = {80, 40, 20};
__device__ __constant__ int c_lvl_start[NLEV] = {0, 6400, 8000};

// ---------------- scratch (device globals; no cudaMalloc allowed) ----------------
__device__ float g_vproj[BATCH * LV * CDIM];   // projected value, (n, pos, h*32+d)
__device__ float g_loc [NQ * TPQ * 2];         // sampling locations in [0,1] space
__device__ float g_attn[NQ * TPQ];             // softmaxed attention weights
__device__ float g_agg [NQ * CDIM];            // aggregated pre-out-proj features

// =====================================================================
// Kernel 1: per-query — sampling offsets, attention softmax, locations
// One block per (n,q); 256 threads.
// =====================================================================
__global__ void k_query_head(const float* __restrict__ query,
                             const float* __restrict__ refpts,
                             const float* __restrict__ W_off,
                             const float* __restrict__ b_off,
                             const float* __restrict__ W_attn,
                             const float* __restrict__ b_attn)
{
    const int nq  = blockIdx.x;            // 0..4799
    const int tid = threadIdx.x;

    __shared__ float q_s[CDIM];
    __shared__ float off_s[TPQ * 2];       // 192
    __shared__ float att_s[TPQ];           // 96

    q_s[tid] = query[nq * CDIM + tid];
    __syncthreads();

    // 288 dot products over K=256 (coalesced across threads at fixed c)
    for (int j = tid; j < TPQ * 2 + TPQ; j += blockDim.x) {
        float acc = 0.f;
        if (j < TPQ * 2) {
            const float* w = W_off + j;
            #pragma unroll 8
            for (int c = 0; c < CDIM; c++) acc += q_s[c] * w[c * (TPQ * 2)];
            off_s[j] = acc + b_off[j];
        } else {
            const int jj = j - TPQ * 2;
            const float* w = W_attn + jj;
            #pragma unroll 8
            for (int c = 0; c < CDIM; c++) acc += q_s[c] * w[c * TPQ];
            att_s[jj] = acc + b_attn[jj];
        }
    }
    __syncthreads();

    // softmax over L*P = 12 per head (8 threads)
    if (tid < NHEADS) {
        float* a = att_s + tid * (NLEV * NPTS);
        float m = a[0];
        #pragma unroll
        for (int i = 1; i < NLEV * NPTS; i++) m = fmaxf(m, a[i]);
        float s = 0.f;
        #pragma unroll
        for (int i = 0; i < NLEV * NPTS; i++) { a[i] = expf(a[i] - m); s += a[i]; }
        float inv = 1.f / s;
        #pragma unroll
        for (int i = 0; i < NLEV * NPTS; i++) a[i] *= inv;
    }
    __syncthreads();

    // sampling locations: loc = ref_cxcy + off/P * ref_wh * 0.5
    if (tid < TPQ * 2) {
        const int j  = tid;
        const int xy = j & 1;
        const int rem = (j >> 1);           // (h*L + l)*P + p
        const int l  = (rem / NPTS) % NLEV;
        const float* rp = refpts + (nq * NLEV + l) * 4;
        float loc = rp[xy] + off_s[j] * (1.f / NPTS) * rp[2 + xy] * 0.5f;
        g_loc[nq * (TPQ * 2) + j] = loc;
    }
    if (tid < TPQ) g_attn[nq * TPQ + tid] = att_s[tid];
}

// =====================================================================
// Kernel 2: value projection GEMM  g_vproj = value @ W_val + b_val
// BM=BN=64, BK=16, 256 threads, 4x4 micro-tile.
// =====================================================================
#define BM 64
#define BN 64
#define BK 16
#define TM 4
#define TN 4

__device__ __forceinline__ void gemm_tile(const float* __restrict__ A,
                                          const float* __restrict__ B,
                                          const float* __restrict__ bias,
                                          float* __restrict__ C,
                                          int M, int Ncols, int K)
{
    __shared__ float As[BK][BM + 1];
    __shared__ float Bs[BK][BN];

    const int tx = threadIdx.x % (BN / TN);   // 0..15
    const int ty = threadIdx.x / (BN / TN);   // 0..15
    const int row0 = blockIdx.y * BM;
    const int col0 = blockIdx.x * BN;

    float acc[TM][TN];
    #pragma unroll
    for (int i = 0; i < TM; i++)
        #pragma unroll
        for (int j = 0; j < TN; j++) acc[i][j] = 0.f;

    for (int k0 = 0; k0 < K; k0 += BK) {
        #pragma unroll
        for (int i = threadIdx.x; i < BM * BK; i += 256) {
            int r = i / BK, c = i % BK;
            As[c][r] = A[(size_t)(row0 + r) * K + k0 + c];
        }
        #pragma unroll
        for (int i = threadIdx.x; i < BK * BN; i += 256) {
            int r = i / BN, c = i % BN;
            Bs[r][c] = B[(size_t)(k0 + r) * Ncols + col0 + c];
        }
        __syncthreads();

        #pragma unroll
        for (int kk = 0; kk < BK; kk++) {
            float ra[TM], rb[TN];
            #pragma unroll
            for (int i = 0; i < TM; i++) ra[i] = As[kk][ty * TM + i];
            #pragma unroll
            for (int j = 0; j < TN; j++) rb[j] = Bs[kk][tx * TN + j];
            #pragma unroll
            for (int i = 0; i < TM; i++)
                #pragma unroll
                for (int j = 0; j < TN; j++) acc[i][j] += ra[i] * rb[j];
        }
        __syncthreads();
    }

    #pragma unroll
    for (int i = 0; i < TM; i++) {
        const int r = row0 + ty * TM + i;
        #pragma unroll
        for (int j = 0; j < TN; j++) {
            const int cidx = col0 + tx * TN + j;
            C[(size_t)r * Ncols + cidx] = acc[i][j] + bias[cidx];
        }
    }
}

__global__ void k_vproj_gemm(const float* __restrict__ value,
                             const float* __restrict__ W_val,
                             const float* __restrict__ b_val)
{
    gemm_tile(value, W_val, b_val, g_vproj, BATCH * LV, CDIM, CDIM);
}

__global__ void k_out_gemm(const float* __restrict__ W_out,
                           const float* __restrict__ b_out,
                           float* __restrict__ out)
{
    gemm_tile(g_agg, W_out, b_out, out, NQ, CDIM, CDIM);
}

// =====================================================================
// Kernel 3: bilinear sampling + weighted aggregation
// One block per (n,q); 256 threads = 8 heads x 32 channels.
// =====================================================================
__global__ void k_sample()
{
    const int nq  = blockIdx.x;
    const int tid = threadIdx.x;
    const int h   = tid >> 5;       // head
    const int d   = tid & 31;       // channel within head
    const int n   = nq / LQ;

    __shared__ float loc_s[TPQ * 2];
    __shared__ float att_s[TPQ];

    if (tid < TPQ * 2) loc_s[tid] = g_loc[nq * (TPQ * 2) + tid];
    if (tid < TPQ)     att_s[tid] = g_attn[nq * TPQ + tid];
    __syncthreads();

    const float* vbase = g_vproj + (size_t)n * LV * CDIM + h * HDIM + d;

    float acc = 0.f;
    #pragma unroll
    for (int l = 0; l < NLEV; l++) {
        const int wl = c_lvl_w[l], hl = c_lvl_h[l], st = c_lvl_start[l];
        #pragma unroll
        for (int p = 0; p < NPTS; p++) {
            const int idx = (h * NLEV + l) * NPTS + p;
            const float aw = att_s[idx];
            const float fx = loc_s[idx * 2 + 0] * (float)wl - 0.5f;
            const float fy = loc_s[idx * 2 + 1] * (float)hl - 0.5f;
            const float x0f = floorf(fx), y0f = floorf(fy);
            const int x0 = (int)x0f, y0 = (int)y0f;
            const float wx = fx - x0f, wy = fy - y0f;

            float v00 = 0.f, v01 = 0.f, v10 = 0.f, v11 = 0.f;
            const bool xin0 = (x0 >= 0) && (x0 < wl);
            const bool xin1 = (x0 + 1 >= 0) && (x0 + 1 < wl);
            const bool yin0 = (y0 >= 0) && (y0 < hl);
            const bool yin1 = (y0 + 1 >= 0) && (y0 + 1 < hl);
            if (yin0) {
                const float* row = vbase + (size_t)(st + y0 * wl) * CDIM;
                if (xin0) v00 = row[(size_t)x0 * CDIM];
                if (xin1) v01 = row[(size_t)(x0 + 1) * CDIM];
            }
            if (yin1) {
                const float* row = vbase + (size_t)(st + (y0 + 1) * wl) * CDIM;
                if (xin0) v10 = row[(size_t)x0 * CDIM];
                if (xin1) v11 = row[(size_t)(x0 + 1) * CDIM];
            }
            const float bil = v00 * (1.f - wx) * (1.f - wy)
                            + v01 * wx * (1.f - wy)
                            + v10 * (1.f - wx) * wy
                            + v11 * wx * wy;
            acc += aw * bil;
        }
    }
    g_agg[(size_t)nq * CDIM + tid] = acc;   // channel = h*32 + d = tid
}

// =====================================================================
// launch — kernel launches ONLY (graph-capturable, allocation-free)
// =====================================================================
extern "C" void kernel_launch(void* const* d_in, const int* in_sizes, int n_in,
                              void* d_out, int out_size)
{
    const float* query  = (const float*)d_in[0];
    const float* refpts = (const float*)d_in[1];
    const float* value  = (const float*)d_in[2];
    const float* W_off  = (const float*)d_in[3];
    const float* b_off  = (const float*)d_in[4];
    const float* W_attn = (const float*)d_in[5];
    const float* b_attn = (const float*)d_in[6];
    const float* W_val  = (const float*)d_in[7];
    const float* b_val  = (const float*)d_in[8];
    const float* W_out  = (const float*)d_in[9];
    const float* b_out  = (const float*)d_in[10];
    float* out = (float*)d_out;

    // 1. query head: offsets + softmax + sampling locations
    k_query_head<<<NQ, 256>>>(query, refpts, W_off, b_off, W_attn, b_attn);

    // 2. value projection: (BATCH*LV x 256) @ (256 x 256) + b_val
    {
        dim3 grid(CDIM / BN, (BATCH * LV) / BM);
        k_vproj_gemm<<<grid, 256>>>(value, W_val, b_val);
    }

    // 3. deformable sampling + aggregation
    k_sample<<<NQ, 256>>>();

    // 4. output projection: (4800 x 256) @ (256 x 256) + b_out
    {
        dim3 grid(CDIM / BN, NQ / BM);
        k_out_gemm<<<grid, 256>>>(W_out, b_out, out);
    }
}

// round 3
// speedup vs baseline: 3.0551x; 3.0551x over previous
#include <cuda_runtime.h>
#include <math.h>

// ---------------- problem constants ----------------
#define BATCH   16
#define LQ      300
#define CDIM    256
#define NHEADS  8
#define NLEV    3
#define NPTS    4
#define HDIM    32
#define LV      8400
#define TPQ     (NHEADS*NLEV*NPTS)   // 96
#define NQ      (BATCH*LQ)           // 4800

__device__ __constant__ int c_lvl_w[NLEV]     = {80, 40, 20};
__device__ __constant__ int c_lvl_h[NLEV]     = {80, 40, 20};
__device__ __constant__ int c_lvl_start[NLEV] = {0, 6400, 8000};

// ---------------- scratch ----------------
__device__ float g_S   [NQ * NHEADS * CDIM];   // aw-weighted sampled RAW value, (nq, h, c)
__device__ float g_wsum[NQ * NHEADS];          // total effective weight per (nq, h)
__device__ float g_loc [NQ * TPQ * 2];
__device__ float g_attn[NQ * TPQ];
__device__ float g_agg [NQ * CDIM];            // after per-head W_val projection

// =====================================================================
// Kernel 1: per-query — offsets, attention softmax, sampling locations
// =====================================================================
__global__ void k_query_head(const float* __restrict__ query,
                             const float* __restrict__ refpts,
                             const float* __restrict__ W_off,
                             const float* __restrict__ b_off,
                             const float* __restrict__ W_attn,
                             const float* __restrict__ b_attn)
{
    const int nq  = blockIdx.x;
    const int tid = threadIdx.x;

    __shared__ float q_s[CDIM];
    __shared__ float off_s[TPQ * 2];
    __shared__ float att_s[TPQ];

    q_s[tid] = query[nq * CDIM + tid];
    __syncthreads();

    for (int j = tid; j < TPQ * 2 + TPQ; j += blockDim.x) {
        float acc = 0.f;
        if (j < TPQ * 2) {
            const float* w = W_off + j;
            #pragma unroll 8
            for (int c = 0; c < CDIM; c++) acc += q_s[c] * w[c * (TPQ * 2)];
            off_s[j] = acc + b_off[j];
        } else {
            const int jj = j - TPQ * 2;
            const float* w = W_attn + jj;
            #pragma unroll 8
            for (int c = 0; c < CDIM; c++) acc += q_s[c] * w[c * TPQ];
            att_s[jj] = acc + b_attn[jj];
        }
    }
    __syncthreads();

    if (tid < NHEADS) {
        float* a = att_s + tid * (NLEV * NPTS);
        float m = a[0];
        #pragma unroll
        for (int i = 1; i < NLEV * NPTS; i++) m = fmaxf(m, a[i]);
        float s = 0.f;
        #pragma unroll
        for (int i = 0; i < NLEV * NPTS; i++) { a[i] = expf(a[i] - m); s += a[i]; }
        float inv = 1.f / s;
        #pragma unroll
        for (int i = 0; i < NLEV * NPTS; i++) a[i] *= inv;
    }
    __syncthreads();

    if (tid < TPQ * 2) {
        const int j  = tid;
        const int xy = j & 1;
        const int rem = (j >> 1);
        const int l  = (rem / NPTS) % NLEV;
        const float* rp = refpts + (nq * NLEV + l) * 4;
        g_loc[nq * (TPQ * 2) + j] = rp[xy] + off_s[j] * (1.f / NPTS) * rp[2 + xy] * 0.5f;
    }
    if (tid < TPQ) g_attn[nq * TPQ + tid] = att_s[tid];
}

// =====================================================================
// Kernel 2: raw-value sampling + attention aggregation.
//   S[nq,h,c] = sum_{l,p} aw * bilinear(value[n, pos, c])
//   wsum[nq,h] = sum_{l,p} aw * (in-bounds corner-weight sum)
// Block per nq; 256 threads = 64 float4-lanes (tx) x 4 groups (ty);
// group ty handles heads {ty, ty+4}.
// =====================================================================
__global__ void __launch_bounds__(256, 4) k_sample_raw(const float* __restrict__ value)
{
    const int nq  = blockIdx.x;
    const int tid = threadIdx.x;
    const int tx  = tid & 63;        // channel float4 lane
    const int ty  = tid >> 6;        // 0..3
    const int n   = nq / LQ;

    __shared__ float loc_s[TPQ * 2];
    __shared__ float att_s[TPQ];

    if (tid < TPQ * 2) loc_s[tid] = g_loc[nq * (TPQ * 2) + tid];
    if (tid < TPQ)     att_s[tid] = g_attn[nq * TPQ + tid];
    __syncthreads();

    const float4* vbase = (const float4*)(value + (size_t)n * LV * CDIM) + tx;
    // stride between spatial positions in float4 units: CDIM/4 = 64

    #pragma unroll
    for (int hh = 0; hh < 2; hh++) {
        const int h = ty + hh * 4;
        float4 acc = make_float4(0.f, 0.f, 0.f, 0.f);
        float wsum = 0.f;
        #pragma unroll
        for (int l = 0; l < NLEV; l++) {
            const int wl = c_lvl_w[l], hl = c_lvl_h[l], st = c_lvl_start[l];
            #pragma unroll
            for (int p = 0; p < NPTS; p++) {
                const int idx = (h * NLEV + l) * NPTS + p;
                const float aw = att_s[idx];
                const float fx = loc_s[idx * 2 + 0] * (float)wl - 0.5f;
                const float fy = loc_s[idx * 2 + 1] * (float)hl - 0.5f;
                const float x0f = floorf(fx), y0f = floorf(fy);
                const int x0 = (int)x0f, y0 = (int)y0f;
                const float wx = fx - x0f, wy = fy - y0f;

                const bool xin0 = (x0 >= 0) && (x0 < wl);
                const bool xin1 = (x0 + 1 < wl) && (x0 + 1 >= 0);
                const bool yin0 = (y0 >= 0) && (y0 < hl);
                const bool yin1 = (y0 + 1 < hl) && (y0 + 1 >= 0);

                const float w00 = (xin0 && yin0) ? (1.f - wx) * (1.f - wy) : 0.f;
                const float w01 = (xin1 && yin0) ? wx * (1.f - wy)         : 0.f;
                const float w10 = (xin0 && yin1) ? (1.f - wx) * wy         : 0.f;
                const float w11 = (xin1 && yin1) ? wx * wy                 : 0.f;

                wsum += aw * (w00 + w01 + w10 + w11);

                const int r0 = st + y0 * wl;
                const int r1 = r0 + wl;
                if (w00 > 0.f) {
                    float4 v = vbase[(size_t)(r0 + x0) * 64];
                    float c = aw * w00;
                    acc.x += c * v.x; acc.y += c * v.y; acc.z += c * v.z; acc.w += c * v.w;
                }
                if (w01 > 0.f) {
                    float4 v = vbase[(size_t)(r0 + x0 + 1) * 64];
                    float c = aw * w01;
                    acc.x += c * v.x; acc.y += c * v.y; acc.z += c * v.z; acc.w += c * v.w;
                }
                if (w10 > 0.f) {
                    float4 v = vbase[(size_t)(r1 + x0) * 64];
                    float c = aw * w10;
                    acc.x += c * v.x; acc.y += c * v.y; acc.z += c * v.z; acc.w += c * v.w;
                }
                if (w11 > 0.f) {
                    float4 v = vbase[(size_t)(r1 + x0 + 1) * 64];
                    float c = aw * w11;
                    acc.x += c * v.x; acc.y += c * v.y; acc.z += c * v.z; acc.w += c * v.w;
                }
            }
        }
        ((float4*)(g_S + ((size_t)nq * NHEADS + h) * CDIM))[tx] = acc;
        if (tx == 0) g_wsum[nq * NHEADS + h] = wsum;
    }
}

// =====================================================================
// Kernel 3: per-head projection
//   agg[nq, h*32+d] = S[nq,h,:] @ W_val[:, h*32+d] + wsum[nq,h]*b_val[h*32+d]
// grid: (M/64 tiles, heads). BM=64, BN=32, BK=16, 256 threads, 4x2 micro.
// =====================================================================
__global__ void __launch_bounds__(256) k_head_proj(const float* __restrict__ W_val,
                                                   const float* __restrict__ b_val)
{
    const int h    = blockIdx.y;
    const int row0 = blockIdx.x * 64;

    __shared__ float As[16][64 + 1];
    __shared__ float Bs[16][32];

    const int tx = threadIdx.x % 16;   // col group (2 cols)
    const int ty = threadIdx.x / 16;   // row group (4 rows)

    float acc[4][2] = {};

    const float* A = g_S + (size_t)h * CDIM;          // row stride = 2048
    const float* B = W_val + h * HDIM;                // col offset; row stride 256

    for (int k0 = 0; k0 < CDIM; k0 += 16) {
        #pragma unroll
        for (int i = threadIdx.x; i < 64 * 16; i += 256) {
            int r = i / 16, c = i % 16;
            As[c][r] = A[(size_t)(row0 + r) * (NHEADS * CDIM) + k0 + c];
        }
        #pragma unroll
        for (int i = threadIdx.x; i < 16 * 32; i += 256) {
            int r = i / 32, c = i % 32;
            Bs[r][c] = B[(size_t)(k0 + r) * CDIM + c];
        }
        __syncthreads();
        #pragma unroll
        for (int kk = 0; kk < 16; kk++) {
            float ra[4], rb[2];
            #pragma unroll
            for (int i = 0; i < 4; i++) ra[i] = As[kk][ty * 4 + i];
            #pragma unroll
            for (int j = 0; j < 2; j++) rb[j] = Bs[kk][tx * 2 + j];
            #pragma unroll
            for (int i = 0; i < 4; i++)
                #pragma unroll
                for (int j = 0; j < 2; j++) acc[i][j] += ra[i] * rb[j];
        }
        __syncthreads();
    }

    #pragma unroll
    for (int i = 0; i < 4; i++) {
        const int r = row0 + ty * 4 + i;
        const float ws = g_wsum[r * NHEADS + h];
        #pragma unroll
        for (int j = 0; j < 2; j++) {
            const int cc = tx * 2 + j;
            g_agg[(size_t)r * CDIM + h * HDIM + cc] = acc[i][j] + ws * b_val[h * HDIM + cc];
        }
    }
}

// =====================================================================
// Kernel 4: output projection  out = agg @ W_out + b_out
// BM=BN=64, BK=16, 256 threads, 4x4 micro.
// =====================================================================
__global__ void __launch_bounds__(256) k_out_gemm(const float* __restrict__ W_out,
                                                  const float* __restrict__ b_out,
                                                  float* __restrict__ out)
{
    __shared__ float As[16][64 + 1];
    __shared__ float Bs[16][64];

    const int tx = threadIdx.x % 16;
    const int ty = threadIdx.x / 16;
    const int row0 = blockIdx.y * 64;
    const int col0 = blockIdx.x * 64;

    float acc[4][4] = {};

    for (int k0 = 0; k0 < CDIM; k0 += 16) {
        #pragma unroll
        for (int i = threadIdx.x; i < 64 * 16; i += 256) {
            int r = i / 16, c = i % 16;
            As[c][r] = g_agg[(size_t)(row0 + r) * CDIM + k0 + c];
        }
        #pragma unroll
        for (int i = threadIdx.x; i < 16 * 64; i += 256) {
            int r = i / 64, c = i % 64;
            Bs[r][c] = W_out[(size_t)(k0 + r) * CDIM + col0 + c];
        }
        __syncthreads();
        #pragma unroll
        for (int kk = 0; kk < 16; kk++) {
            float ra[4], rb[4];
            #pragma unroll
            for (int i = 0; i < 4; i++) ra[i] = As[kk][ty * 4 + i];
            #pragma unroll
            for (int j = 0; j < 4; j++) rb[j] = Bs[kk][tx * 4 + j];
            #pragma unroll
            for (int i = 0; i < 4; i++)
                #pragma unroll
                for (int j = 0; j < 4; j++) acc[i][j] += ra[i] * rb[j];
        }
        __syncthreads();
    }

    #pragma unroll
    for (int i = 0; i < 4; i++) {
        const int r = row0 + ty * 4 + i;
        #pragma unroll
        for (int j = 0; j < 4; j++) {
            const int c = col0 + tx * 4 + j;
            out[(size_t)r * CDIM + c] = acc[i][j] + b_out[c];
        }
    }
}

// =====================================================================
// launch
// =====================================================================
extern "C" void kernel_launch(void* const* d_in, const int* in_sizes, int n_in,
                              void* d_out, int out_size)
{
    const float* query  = (const float*)d_in[0];
    const float* refpts = (const float*)d_in[1];
    const float* value  = (const float*)d_in[2];
    const float* W_off  = (const float*)d_in[3];
    const float* b_off  = (const float*)d_in[4];
    const float* W_attn = (const float*)d_in[5];
    const float* b_attn = (const float*)d_in[6];
    const float* W_val  = (const float*)d_in[7];
    const float* b_val  = (const float*)d_in[8];
    const float* W_out  = (const float*)d_in[9];
    const float* b_out  = (const float*)d_in[10];
    float* out = (float*)d_out;

    k_query_head<<<NQ, 256>>>(query, refpts, W_off, b_off, W_attn, b_attn);

    k_sample_raw<<<NQ, 256>>>(value);

    {
        dim3 grid(NQ / 64, NHEADS);
        k_head_proj<<<grid, 256>>>(W_val, b_val);
    }
    {
        dim3 grid(CDIM / 64, NQ / 64);
        k_out_gemm<<<grid, 256>>>(W_out, b_out, out);
    }
}

// round 4
// speedup vs baseline: 3.7571x; 1.2298x over previous
#include <cuda_runtime.h>
#include <math.h>

// ---------------- problem constants ----------------
#define BATCH   16
#define LQ      300
#define CDIM    256
#define NHEADS  8
#define NLEV    3
#define NPTS    4
#define HDIM    32
#define LV      8400
#define TPQ     (NHEADS*NLEV*NPTS)   // 96
#define NQ      (BATCH*LQ)           // 4800
#define NLOGIT  (TPQ*2 + TPQ)        // 288

__device__ __constant__ int c_lvl_w[NLEV]     = {80, 40, 20};
__device__ __constant__ int c_lvl_h[NLEV]     = {80, 40, 20};
__device__ __constant__ int c_lvl_start[NLEV] = {0, 6400, 8000};

// ---------------- scratch ----------------
__device__ float g_logits[NQ * NLOGIT];        // [nq][288]: 0..191 off, 192..287 attn
__device__ float g_S   [NQ * NHEADS * CDIM];   // aw-weighted sampled RAW value
__device__ float g_wsum[NQ * NHEADS];
__device__ float g_loc [NQ * TPQ * 2];
__device__ float g_attn[NQ * TPQ];
__device__ float g_agg [NQ * CDIM];

// =====================================================================
// Kernel 1a: query logits GEMM
//   g_logits[:, col_off : col_off+N] = query @ B + bias
// BM=64, BN=32, BK=16, 256 threads, 4x2 micro-tile.
// =====================================================================
__global__ void __launch_bounds__(256) k_qgemm(const float* __restrict__ A,
                                               const float* __restrict__ B,
                                               const float* __restrict__ bias,
                                               int Ncols, int col_off)
{
    const int row0 = blockIdx.y * 64;
    const int col0 = blockIdx.x * 32;

    __shared__ float As[16][64 + 1];
    __shared__ float Bs[16][32];

    const int tx = threadIdx.x % 16;   // 2 cols each
    const int ty = threadIdx.x / 16;   // 4 rows each

    float acc[4][2] = {};

    for (int k0 = 0; k0 < CDIM; k0 += 16) {
        #pragma unroll
        for (int i = threadIdx.x; i < 64 * 16; i += 256) {
            int r = i / 16, c = i % 16;
            As[c][r] = A[(size_t)(row0 + r) * CDIM + k0 + c];
        }
        #pragma unroll
        for (int i = threadIdx.x; i < 16 * 32; i += 256) {
            int r = i / 32, c = i % 32;
            Bs[r][c] = B[(size_t)(k0 + r) * Ncols + col0 + c];
        }
        __syncthreads();
        #pragma unroll
        for (int kk = 0; kk < 16; kk++) {
            float ra[4], rb[2];
            #pragma unroll
            for (int i = 0; i < 4; i++) ra[i] = As[kk][ty * 4 + i];
            #pragma unroll
            for (int j = 0; j < 2; j++) rb[j] = Bs[kk][tx * 2 + j];
            #pragma unroll
            for (int i = 0; i < 4; i++)
                #pragma unroll
                for (int j = 0; j < 2; j++) acc[i][j] += ra[i] * rb[j];
        }
        __syncthreads();
    }

    #pragma unroll
    for (int i = 0; i < 4; i++) {
        const int r = row0 + ty * 4 + i;
        #pragma unroll
        for (int j = 0; j < 2; j++) {
            const int c = col0 + tx * 2 + j;
            g_logits[(size_t)r * NLOGIT + col_off + c] = acc[i][j] + bias[c];
        }
    }
}

// =====================================================================
// Kernel 1b: per-query epilogue — softmax + sampling locations
// One block per nq; 192 threads.
// =====================================================================
__global__ void __launch_bounds__(192) k_qpost(const float* __restrict__ refpts)
{
    const int nq  = blockIdx.x;
    const int tid = threadIdx.x;

    __shared__ float att_s[TPQ];

    if (tid < TPQ) att_s[tid] = g_logits[(size_t)nq * NLOGIT + TPQ * 2 + tid];
    __syncthreads();

    if (tid < NHEADS) {
        float* a = att_s + tid * (NLEV * NPTS);
        float m = a[0];
        #pragma unroll
        for (int i = 1; i < NLEV * NPTS; i++) m = fmaxf(m, a[i]);
        float s = 0.f;
        #pragma unroll
        for (int i = 0; i < NLEV * NPTS; i++) { a[i] = expf(a[i] - m); s += a[i]; }
        float inv = 1.f / s;
        #pragma unroll
        for (int i = 0; i < NLEV * NPTS; i++) a[i] *= inv;
    }
    __syncthreads();

    // sampling locations (192 entries, one per thread)
    {
        const int j  = tid;
        const int xy = j & 1;
        const int rem = (j >> 1);
        const int l  = (rem / NPTS) % NLEV;
        const float* rp = refpts + (nq * NLEV + l) * 4;
        const float off = g_logits[(size_t)nq * NLOGIT + j];
        g_loc[nq * (TPQ * 2) + j] = rp[xy] + off * (1.f / NPTS) * rp[2 + xy] * 0.5f;
    }
    if (tid < TPQ) g_attn[nq * TPQ + tid] = att_s[tid];
}

// =====================================================================
// Kernel 2: raw-value sampling + attention aggregation.
// Block per nq; 256 threads = 64 float4-lanes x 4 groups; each group
// handles heads {ty, ty+4}.
// =====================================================================
__global__ void __launch_bounds__(256, 4) k_sample_raw(const float* __restrict__ value)
{
    const int nq  = blockIdx.x;
    const int tid = threadIdx.x;
    const int tx  = tid & 63;
    const int ty  = tid >> 6;
    const int n   = nq / LQ;

    __shared__ float loc_s[TPQ * 2];
    __shared__ float att_s[TPQ];

    if (tid < TPQ * 2) loc_s[tid] = g_loc[nq * (TPQ * 2) + tid];
    if (tid < TPQ)     att_s[tid] = g_attn[nq * TPQ + tid];
    __syncthreads();

    const float4* vbase = (const float4*)(value + (size_t)n * LV * CDIM) + tx;

    #pragma unroll
    for (int hh = 0; hh < 2; hh++) {
        const int h = ty + hh * 4;
        float4 acc = make_float4(0.f, 0.f, 0.f, 0.f);
        float wsum = 0.f;
        #pragma unroll
        for (int l = 0; l < NLEV; l++) {
            const int wl = c_lvl_w[l], hl = c_lvl_h[l], st = c_lvl_start[l];
            #pragma unroll
            for (int p = 0; p < NPTS; p++) {
                const int idx = (h * NLEV + l) * NPTS + p;
                const float aw = att_s[idx];
                const float fx = loc_s[idx * 2 + 0] * (float)wl - 0.5f;
                const float fy = loc_s[idx * 2 + 1] * (float)hl - 0.5f;
                const float x0f = floorf(fx), y0f = floorf(fy);
                const int x0 = (int)x0f, y0 = (int)y0f;
                const float wx = fx - x0f, wy = fy - y0f;

                const bool xin0 = (x0 >= 0) && (x0 < wl);
                const bool xin1 = (x0 + 1 < wl) && (x0 + 1 >= 0);
                const bool yin0 = (y0 >= 0) && (y0 < hl);
                const bool yin1 = (y0 + 1 < hl) && (y0 + 1 >= 0);

                const float w00 = (xin0 && yin0) ? (1.f - wx) * (1.f - wy) : 0.f;
                const float w01 = (xin1 && yin0) ? wx * (1.f - wy)         : 0.f;
                const float w10 = (xin0 && yin1) ? (1.f - wx) * wy         : 0.f;
                const float w11 = (xin1 && yin1) ? wx * wy                 : 0.f;

                wsum += aw * (w00 + w01 + w10 + w11);

                const int r0 = st + y0 * wl;
                const int r1 = r0 + wl;
                if (w00 > 0.f) {
                    float4 v = vbase[(size_t)(r0 + x0) * 64];
                    float c = aw * w00;
                    acc.x += c * v.x; acc.y += c * v.y; acc.z += c * v.z; acc.w += c * v.w;
                }
                if (w01 > 0.f) {
                    float4 v = vbase[(size_t)(r0 + x0 + 1) * 64];
                    float c = aw * w01;
                    acc.x += c * v.x; acc.y += c * v.y; acc.z += c * v.z; acc.w += c * v.w;
                }
                if (w10 > 0.f) {
                    float4 v = vbase[(size_t)(r1 + x0) * 64];
                    float c = aw * w10;
                    acc.x += c * v.x; acc.y += c * v.y; acc.z += c * v.z; acc.w += c * v.w;
                }
                if (w11 > 0.f) {
                    float4 v = vbase[(size_t)(r1 + x0 + 1) * 64];
                    float c = aw * w11;
                    acc.x += c * v.x; acc.y += c * v.y; acc.z += c * v.z; acc.w += c * v.w;
                }
            }
        }
        ((float4*)(g_S + ((size_t)nq * NHEADS + h) * CDIM))[tx] = acc;
        if (tx == 0) g_wsum[nq * NHEADS + h] = wsum;
    }
}

// =====================================================================
// Kernel 3: per-head projection
// =====================================================================
__global__ void __launch_bounds__(256) k_head_proj(const float* __restrict__ W_val,
                                                   const float* __restrict__ b_val)
{
    const int h    = blockIdx.y;
    const int row0 = blockIdx.x * 64;

    __shared__ float As[16][64 + 1];
    __shared__ float Bs[16][32];

    const int tx = threadIdx.x % 16;
    const int ty = threadIdx.x / 16;

    float acc[4][2] = {};

    const float* A = g_S + (size_t)h * CDIM;
    const float* B = W_val + h * HDIM;

    for (int k0 = 0; k0 < CDIM; k0 += 16) {
        #pragma unroll
        for (int i = threadIdx.x; i < 64 * 16; i += 256) {
            int r = i / 16, c = i % 16;
            As[c][r] = A[(size_t)(row0 + r) * (NHEADS * CDIM) + k0 + c];
        }
        #pragma unroll
        for (int i = threadIdx.x; i < 16 * 32; i += 256) {
            int r = i / 32, c = i % 32;
            Bs[r][c] = B[(size_t)(k0 + r) * CDIM + c];
        }
        __syncthreads();
        #pragma unroll
        for (int kk = 0; kk < 16; kk++) {
            float ra[4], rb[2];
            #pragma unroll
            for (int i = 0; i < 4; i++) ra[i] = As[kk][ty * 4 + i];
            #pragma unroll
            for (int j = 0; j < 2; j++) rb[j] = Bs[kk][tx * 2 + j];
            #pragma unroll
            for (int i = 0; i < 4; i++)
                #pragma unroll
                for (int j = 0; j < 2; j++) acc[i][j] += ra[i] * rb[j];
        }
        __syncthreads();
    }

    #pragma unroll
    for (int i = 0; i < 4; i++) {
        const int r = row0 + ty * 4 + i;
        const float ws = g_wsum[r * NHEADS + h];
        #pragma unroll
        for (int j = 0; j < 2; j++) {
            const int cc = tx * 2 + j;
            g_agg[(size_t)r * CDIM + h * HDIM + cc] = acc[i][j] + ws * b_val[h * HDIM + cc];
        }
    }
}

// =====================================================================
// Kernel 4: output projection
// =====================================================================
__global__ void __launch_bounds__(256) k_out_gemm(const float* __restrict__ W_out,
                                                  const float* __restrict__ b_out,
                                                  float* __restrict__ out)
{
    __shared__ float As[16][64 + 1];
    __shared__ float Bs[16][64];

    const int tx = threadIdx.x % 16;
    const int ty = threadIdx.x / 16;
    const int row0 = blockIdx.y * 64;
    const int col0 = blockIdx.x * 64;

    float acc[4][4] = {};

    for (int k0 = 0; k0 < CDIM; k0 += 16) {
        #pragma unroll
        for (int i = threadIdx.x; i < 64 * 16; i += 256) {
            int r = i / 16, c = i % 16;
            As[c][r] = g_agg[(size_t)(row0 + r) * CDIM + k0 + c];
        }
        #pragma unroll
        for (int i = threadIdx.x; i < 16 * 64; i += 256) {
            int r = i / 64, c = i % 64;
            Bs[r][c] = W_out[(size_t)(k0 + r) * CDIM + col0 + c];
        }
        __syncthreads();
        #pragma unroll
        for (int kk = 0; kk < 16; kk++) {
            float ra[4], rb[4];
            #pragma unroll
            for (int i = 0; i < 4; i++) ra[i] = As[kk][ty * 4 + i];
            #pragma unroll
            for (int j = 0; j < 4; j++) rb[j] = Bs[kk][tx * 4 + j];
            #pragma unroll
            for (int i = 0; i < 4; i++)
                #pragma unroll
                for (int j = 0; j < 4; j++) acc[i][j] += ra[i] * rb[j];
        }
        __syncthreads();
    }

    #pragma unroll
    for (int i = 0; i < 4; i++) {
        const int r = row0 + ty * 4 + i;
        #pragma unroll
        for (int j = 0; j < 4; j++) {
            const int c = col0 + tx * 4 + j;
            out[(size_t)r * CDIM + c] = acc[i][j] + b_out[c];
        }
    }
}

// =====================================================================
// launch
// =====================================================================
extern "C" void kernel_launch(void* const* d_in, const int* in_sizes, int n_in,
                              void* d_out, int out_size)
{
    const float* query  = (const float*)d_in[0];
    const float* refpts = (const float*)d_in[1];
    const float* value  = (const float*)d_in[2];
    const float* W_off  = (const float*)d_in[3];
    const float* b_off  = (const float*)d_in[4];
    const float* W_attn = (const float*)d_in[5];
    const float* b_attn = (const float*)d_in[6];
    const float* W_val  = (const float*)d_in[7];
    const float* b_val  = (const float*)d_in[8];
    const float* W_out  = (const float*)d_in[9];
    const float* b_out  = (const float*)d_in[10];
    float* out = (float*)d_out;

    // 1a. query logits GEMMs (off: N=192, attn: N=96)
    {
        dim3 goff(192 / 32, NQ / 64);
        k_qgemm<<<goff, 256>>>(query, W_off, b_off, 192, 0);
        dim3 gattn(96 / 32, NQ / 64);
        k_qgemm<<<gattn, 256>>>(query, W_attn, b_attn, 96, TPQ * 2);
    }
    // 1b. softmax + sampling locations
    k_qpost<<<NQ, 192>>>(refpts);

    // 2. raw-value sampling + aggregation
    k_sample_raw<<<NQ, 256>>>(value);

    // 3. per-head W_val projection
    {
        dim3 grid(NQ / 64, NHEADS);
        k_head_proj<<<grid, 256>>>(W_val, b_val);
    }
    // 4. output projection
    {
        dim3 grid(CDIM / 64, NQ / 64);
        k_out_gemm<<<grid, 256>>>(W_out, b_out, out);
    }
}

// round 5
// speedup vs baseline: 4.0075x; 1.0667x over previous
#include <cuda_runtime.h>
#include <math.h>

// ---------------- problem constants ----------------
#define BATCH   16
#define LQ      300
#define CDIM    256
#define NHEADS  8
#define NLEV    3
#define NPTS    4
#define HDIM    32
#define LV      8400
#define TPQ     (NHEADS*NLEV*NPTS)   // 96
#define NQ      (BATCH*LQ)           // 4800
#define NLOGIT  (TPQ*2 + TPQ)        // 288

__device__ __constant__ int   c_lvl_w[NLEV]     = {80, 40, 20};
__device__ __constant__ int   c_lvl_h[NLEV]     = {80, 40, 20};
__device__ __constant__ int   c_lvl_start[NLEV] = {0, 6400, 8000};

// ---------------- scratch ----------------
__device__ float g_logits[NQ * NLOGIT];        // [nq][288]: 0..191 off, 192..287 attn
__device__ int   g_ci  [NQ * TPQ * 4];         // clamped corner position indices
__device__ float g_cw  [NQ * TPQ * 4];         // aw-folded corner weights (0 if OOB)
__device__ float g_S   [NQ * NHEADS * CDIM];   // aw-weighted sampled RAW value
__device__ float g_wsum[NQ * NHEADS];
__device__ float g_agg [NQ * CDIM];

// =====================================================================
// Kernel 1a: query logits GEMM  (BM=64, BN=32, BK=16, 256 thr, 4x2)
// =====================================================================
__global__ void __launch_bounds__(256) k_qgemm(const float* __restrict__ A,
                                               const float* __restrict__ B,
                                               const float* __restrict__ bias,
                                               int Ncols, int col_off)
{
    const int row0 = blockIdx.y * 64;
    const int col0 = blockIdx.x * 32;

    __shared__ float As[16][64 + 1];
    __shared__ float Bs[16][32];

    const int tx = threadIdx.x % 16;
    const int ty = threadIdx.x / 16;

    float acc[4][2] = {};

    for (int k0 = 0; k0 < CDIM; k0 += 16) {
        #pragma unroll
        for (int i = threadIdx.x; i < 64 * 16; i += 256) {
            int r = i / 16, c = i % 16;
            As[c][r] = A[(size_t)(row0 + r) * CDIM + k0 + c];
        }
        #pragma unroll
        for (int i = threadIdx.x; i < 16 * 32; i += 256) {
            int r = i / 32, c = i % 32;
            Bs[r][c] = B[(size_t)(k0 + r) * Ncols + col0 + c];
        }
        __syncthreads();
        #pragma unroll
        for (int kk = 0; kk < 16; kk++) {
            float ra[4], rb[2];
            #pragma unroll
            for (int i = 0; i < 4; i++) ra[i] = As[kk][ty * 4 + i];
            #pragma unroll
            for (int j = 0; j < 2; j++) rb[j] = Bs[kk][tx * 2 + j];
            #pragma unroll
            for (int i = 0; i < 4; i++)
                #pragma unroll
                for (int j = 0; j < 2; j++) acc[i][j] += ra[i] * rb[j];
        }
        __syncthreads();
    }

    #pragma unroll
    for (int i = 0; i < 4; i++) {
        const int r = row0 + ty * 4 + i;
        #pragma unroll
        for (int j = 0; j < 2; j++) {
            const int c = col0 + tx * 2 + j;
            g_logits[(size_t)r * NLOGIT + col_off + c] = acc[i][j] + bias[c];
        }
    }
}

// =====================================================================
// Kernel 1b: per-query epilogue — softmax, locations, CORNER PRECOMPUTE
// One block of 96 threads per nq; thread = one (h,l,p) point.
// =====================================================================
__global__ void __launch_bounds__(96) k_qpost(const float* __restrict__ refpts)
{
    const int nq  = blockIdx.x;
    const int tid = threadIdx.x;          // 0..95 = point index

    __shared__ float att_s[TPQ];
    __shared__ float ws_s[TPQ];

    att_s[tid] = g_logits[(size_t)nq * NLOGIT + TPQ * 2 + tid];
    __syncthreads();

    if (tid < NHEADS) {
        float* a = att_s + tid * (NLEV * NPTS);
        float m = a[0];
        #pragma unroll
        for (int i = 1; i < NLEV * NPTS; i++) m = fmaxf(m, a[i]);
        float s = 0.f;
        #pragma unroll
        for (int i = 0; i < NLEV * NPTS; i++) { a[i] = expf(a[i] - m); s += a[i]; }
        float inv = 1.f / s;
        #pragma unroll
        for (int i = 0; i < NLEV * NPTS; i++) a[i] *= inv;
    }
    __syncthreads();

    // per-point corner computation
    const int l  = (tid % (NLEV * NPTS)) / NPTS;
    const int wl = c_lvl_w[l], hl = c_lvl_h[l], st = c_lvl_start[l];
    const float aw = att_s[tid];

    const float offx = g_logits[(size_t)nq * NLOGIT + 2 * tid];
    const float offy = g_logits[(size_t)nq * NLOGIT + 2 * tid + 1];
    const float* rp = refpts + (nq * NLEV + l) * 4;
    const float locx = rp[0] + offx * (1.f / NPTS) * rp[2] * 0.5f;
    const float locy = rp[1] + offy * (1.f / NPTS) * rp[3] * 0.5f;

    const float fx = locx * (float)wl - 0.5f;
    const float fy = locy * (float)hl - 0.5f;
    const float x0f = floorf(fx), y0f = floorf(fy);
    const int x0 = (int)x0f, y0 = (int)y0f;
    const float wx = fx - x0f, wy = fy - y0f;

    const bool xin0 = (x0 >= 0) && (x0 < wl);
    const bool xin1 = (x0 + 1 >= 0) && (x0 + 1 < wl);
    const bool yin0 = (y0 >= 0) && (y0 < hl);
    const bool yin1 = (y0 + 1 >= 0) && (y0 + 1 < hl);

    const float w00 = (xin0 && yin0) ? aw * (1.f - wx) * (1.f - wy) : 0.f;
    const float w01 = (xin1 && yin0) ? aw * wx * (1.f - wy)         : 0.f;
    const float w10 = (xin0 && yin1) ? aw * (1.f - wx) * wy         : 0.f;
    const float w11 = (xin1 && yin1) ? aw * wx * wy                 : 0.f;

    // clamped (always valid) indices
    const int x0c = min(max(x0, 0), wl - 1);
    const int x1c = min(max(x0 + 1, 0), wl - 1);
    const int y0c = min(max(y0, 0), hl - 1);
    const int y1c = min(max(y0 + 1, 0), hl - 1);

    const size_t base = ((size_t)nq * TPQ + tid) * 4;
    g_ci[base + 0] = st + y0c * wl + x0c;
    g_ci[base + 1] = st + y0c * wl + x1c;
    g_ci[base + 2] = st + y1c * wl + x0c;
    g_ci[base + 3] = st + y1c * wl + x1c;
    g_cw[base + 0] = w00;
    g_cw[base + 1] = w01;
    g_cw[base + 2] = w10;
    g_cw[base + 3] = w11;

    ws_s[tid] = w00 + w01 + w10 + w11;
    __syncthreads();

    if (tid < NHEADS) {
        float s = 0.f;
        #pragma unroll
        for (int i = 0; i < NLEV * NPTS; i++) s += ws_s[tid * (NLEV * NPTS) + i];
        g_wsum[nq * NHEADS + tid] = s;
    }
}

// =====================================================================
// Kernel 2: raw-value gather + accumulate (all scalar math precomputed)
// Block per nq; 256 threads = 64 float4-lanes x 4 groups;
// group ty handles heads {ty, ty+4}.
// =====================================================================
__global__ void __launch_bounds__(256, 4) k_sample_raw(const float* __restrict__ value)
{
    const int nq  = blockIdx.x;
    const int tid = threadIdx.x;
    const int tx  = tid & 63;
    const int ty  = tid >> 6;
    const int n   = nq / LQ;

    __shared__ int   ci_s[TPQ * 4];
    __shared__ float cw_s[TPQ * 4];

    #pragma unroll
    for (int i = tid; i < TPQ * 4; i += 256) {
        ci_s[i] = g_ci[(size_t)nq * TPQ * 4 + i];
        cw_s[i] = g_cw[(size_t)nq * TPQ * 4 + i];
    }
    __syncthreads();

    const float4* vbase = (const float4*)(value + (size_t)n * LV * CDIM) + tx;

    #pragma unroll
    for (int hh = 0; hh < 2; hh++) {
        const int h = ty + hh * 4;
        float4 acc = make_float4(0.f, 0.f, 0.f, 0.f);
        #pragma unroll
        for (int j = 0; j < NLEV * NPTS; j++) {
            const int pbase = (h * (NLEV * NPTS) + j) * 4;
            #pragma unroll
            for (int c = 0; c < 4; c++) {
                const float w = cw_s[pbase + c];
                if (w != 0.f) {
                    float4 v = vbase[(size_t)ci_s[pbase + c] * 64];
                    acc.x += w * v.x; acc.y += w * v.y;
                    acc.z += w * v.z; acc.w += w * v.w;
                }
            }
        }
        ((float4*)(g_S + ((size_t)nq * NHEADS + h) * CDIM))[tx] = acc;
    }
}

// =====================================================================
// Kernel 3: per-head projection
// =====================================================================
__global__ void __launch_bounds__(256) k_head_proj(const float* __restrict__ W_val,
                                                   const float* __restrict__ b_val)
{
    const int h    = blockIdx.y;
    const int row0 = blockIdx.x * 64;

    __shared__ float As[16][64 + 1];
    __shared__ float Bs[16][32];

    const int tx = threadIdx.x % 16;
    const int ty = threadIdx.x / 16;

    float acc[4][2] = {};

    const float* A = g_S + (size_t)h * CDIM;
    const float* B = W_val + h * HDIM;

    for (int k0 = 0; k0 < CDIM; k0 += 16) {
        #pragma unroll
        for (int i = threadIdx.x; i < 64 * 16; i += 256) {
            int r = i / 16, c = i % 16;
            As[c][r] = A[(size_t)(row0 + r) * (NHEADS * CDIM) + k0 + c];
        }
        #pragma unroll
        for (int i = threadIdx.x; i < 16 * 32; i += 256) {
            int r = i / 32, c = i % 32;
            Bs[r][c] = B[(size_t)(k0 + r) * CDIM + c];
        }
        __syncthreads();
        #pragma unroll
        for (int kk = 0; kk < 16; kk++) {
            float ra[4], rb[2];
            #pragma unroll
            for (int i = 0; i < 4; i++) ra[i] = As[kk][ty * 4 + i];
            #pragma unroll
            for (int j = 0; j < 2; j++) rb[j] = Bs[kk][tx * 2 + j];
            #pragma unroll
            for (int i = 0; i < 4; i++)
                #pragma unroll
                for (int j = 0; j < 2; j++) acc[i][j] += ra[i] * rb[j];
        }
        __syncthreads();
    }

    #pragma unroll
    for (int i = 0; i < 4; i++) {
        const int r = row0 + ty * 4 + i;
        const float ws = g_wsum[r * NHEADS + h];
        #pragma unroll
        for (int j = 0; j < 2; j++) {
            const int cc = tx * 2 + j;
            g_agg[(size_t)r * CDIM + h * HDIM + cc] = acc[i][j] + ws * b_val[h * HDIM + cc];
        }
    }
}

// =====================================================================
// Kernel 4: output projection
// =====================================================================
__global__ void __launch_bounds__(256) k_out_gemm(const float* __restrict__ W_out,
                                                  const float* __restrict__ b_out,
                                                  float* __restrict__ out)
{
    __shared__ float As[16][64 + 1];
    __shared__ float Bs[16][64];

    const int tx = threadIdx.x % 16;
    const int ty = threadIdx.x / 16;
    const int row0 = blockIdx.y * 64;
    const int col0 = blockIdx.x * 64;

    float acc[4][4] = {};

    for (int k0 = 0; k0 < CDIM; k0 += 16) {
        #pragma unroll
        for (int i = threadIdx.x; i < 64 * 16; i += 256) {
            int r = i / 16, c = i % 16;
            As[c][r] = g_agg[(size_t)(row0 + r) * CDIM + k0 + c];
        }
        #pragma unroll
        for (int i = threadIdx.x; i < 16 * 64; i += 256) {
            int r = i / 64, c = i % 64;
            Bs[r][c] = W_out[(size_t)(k0 + r) * CDIM + col0 + c];
        }
        __syncthreads();
        #pragma unroll
        for (int kk = 0; kk < 16; kk++) {
            float ra[4], rb[4];
            #pragma unroll
            for (int i = 0; i < 4; i++) ra[i] = As[kk][ty * 4 + i];
            #pragma unroll
            for (int j = 0; j < 4; j++) rb[j] = Bs[kk][tx * 4 + j];
            #pragma unroll
            for (int i = 0; i < 4; i++)
                #pragma unroll
                for (int j = 0; j < 4; j++) acc[i][j] += ra[i] * rb[j];
        }
        __syncthreads();
    }

    #pragma unroll
    for (int i = 0; i < 4; i++) {
        const int r = row0 + ty * 4 + i;
        #pragma unroll
        for (int j = 0; j < 4; j++) {
            const int c = col0 + tx * 4 + j;
            out[(size_t)r * CDIM + c] = acc[i][j] + b_out[c];
        }
    }
}

// =====================================================================
// launch
// =====================================================================
extern "C" void kernel_launch(void* const* d_in, const int* in_sizes, int n_in,
                              void* d_out, int out_size)
{
    const float* query  = (const float*)d_in[0];
    const float* refpts = (const float*)d_in[1];
    const float* value  = (const float*)d_in[2];
    const float* W_off  = (const float*)d_in[3];
    const float* b_off  = (const float*)d_in[4];
    const float* W_attn = (const float*)d_in[5];
    const float* b_attn = (const float*)d_in[6];
    const float* W_val  = (const float*)d_in[7];
    const float* b_val  = (const float*)d_in[8];
    const float* W_out  = (const float*)d_in[9];
    const float* b_out  = (const float*)d_in[10];
    float* out = (float*)d_out;

    {
        dim3 goff(192 / 32, NQ / 64);
        k_qgemm<<<goff, 256>>>(query, W_off, b_off, 192, 0);
        dim3 gattn(96 / 32, NQ / 64);
        k_qgemm<<<gattn, 256>>>(query, W_attn, b_attn, 96, TPQ * 2);
    }
    k_qpost<<<NQ, 96>>>(refpts);

    k_sample_raw<<<NQ, 256>>>(value);

    {
        dim3 grid(NQ / 64, NHEADS);
        k_head_proj<<<grid, 256>>>(W_val, b_val);
    }
    {
        dim3 grid(CDIM / 64, NQ / 64);
        k_out_gemm<<<grid, 256>>>(W_out, b_out, out);
    }
}